// round 8
// baseline (speedup 1.0000x reference)
#include <cuda_runtime.h>
#include <cuda_fp16.h>
#include <cstdint>

#define EPSV 1e-7f

// Scratch (no cudaMalloc allowed)
__device__ __align__(16) __half g_Mh[16 * 4 * 1024 * 128];  // normalized m, fp16
__device__ __align__(16) __half g_W2h[128 * 640];           // [b][c*128+a], c=4 -> theta
__device__ __align__(16) __half g_xh[16 * 128 * 1024];      // [s][a][j]  (B for k1)
__device__ __align__(16) __half g_xh2[16 * 1024 * 128];     // [s][j][a]  (L chunk for k2)

// ---------------------------------------------------------------------------
__device__ __forceinline__ uint32_t cvta_s(const void* p) {
    uint32_t a;
    asm("{ .reg .u64 t; cvta.to.shared.u64 t, %1; cvt.u32.u64 %0, t; }"
        : "=r"(a) : "l"(p));
    return a;
}
__device__ __forceinline__ uint32_t swz64(uint32_t off) {  // SW64-style xor swizzle
    return off ^ ((off >> 3) & 0x30);
}
__device__ __forceinline__ void cpa16(uint32_t d, const void* g) {
    asm volatile("cp.async.cg.shared.global [%0], [%1], 16;" :: "r"(d), "l"(g));
}
#define CPA_COMMIT asm volatile("cp.async.commit_group;")
#define CPA_WAIT0  asm volatile("cp.async.wait_group 0;")
#define CPA_WAIT1  asm volatile("cp.async.wait_group 1;")

#define LDSM4(r, addr) \
    asm volatile("ldmatrix.sync.aligned.m8n8.x4.shared.b16 {%0,%1,%2,%3}, [%4];" \
        : "=r"((r)[0]), "=r"((r)[1]), "=r"((r)[2]), "=r"((r)[3]) : "r"(addr))

__device__ __forceinline__ void mma16(float* d, const uint32_t* a, const uint32_t* b) {
    asm volatile(
        "mma.sync.aligned.m16n8k16.row.col.f32.f16.f16.f32 "
        "{%0,%1,%2,%3}, {%4,%5,%6,%7}, {%8,%9}, {%0,%1,%2,%3};"
        : "+f"(d[0]), "+f"(d[1]), "+f"(d[2]), "+f"(d[3])
        : "r"(a[0]), "r"(a[1]), "r"(a[2]), "r"(a[3]), "r"(b[0]), "r"(b[1]));
}
__device__ __forceinline__ float fasttanh(float x) {
    float y; asm("tanh.approx.f32 %0, %1;" : "=f"(y) : "f"(x)); return y;
}

// ---------------------------------------------------------------------------
// k0_w: weight[a][b][c] + theta[a][b] -> g_W2h[b][c*128 + a]  (fp16)
// ---------------------------------------------------------------------------
__global__ void k0_w(const float* __restrict__ w, const float* __restrict__ th) {
    int o = blockIdx.x * 256 + threadIdx.x;   // 16384
    int a = o >> 7, b = o & 127;
    float4 v = *reinterpret_cast<const float4*>(w + (size_t)(a * 128 + b) * 4);
    g_W2h[b * 640 + 0 * 128 + a] = __float2half_rn(v.x);
    g_W2h[b * 640 + 1 * 128 + a] = __float2half_rn(v.y);
    g_W2h[b * 640 + 2 * 128 + a] = __float2half_rn(v.z);
    g_W2h[b * 640 + 3 * 128 + a] = __float2half_rn(v.w);
    g_W2h[b * 640 + 4 * 128 + a] = __float2half_rn(th[a * 128 + b]);
}

// ---------------------------------------------------------------------------
// k0_x: x[s][j][a] fp32 -> g_xh[s][a][j] fp16 (transposed) + g_xh2[s][j][a] fp16
// ---------------------------------------------------------------------------
__global__ void k0_x(const float* __restrict__ x) {
    __shared__ float t[32][132];
    const int tid = threadIdx.x;
    const int j0 = blockIdx.x * 32, s = blockIdx.y;
#pragma unroll
    for (int it = 0; it < 4; it++) {
        int f = tid + it * 256;               // < 1024
        int jj = f >> 5, a4 = (f & 31) * 4;
        float4 v = *reinterpret_cast<const float4*>(
            x + ((size_t)(s * 1024 + j0 + jj)) * 128 + a4);
        t[jj][a4] = v.x; t[jj][a4 + 1] = v.y; t[jj][a4 + 2] = v.z; t[jj][a4 + 3] = v.w;
        __half2 h01 = __floats2half2_rn(v.x, v.y);
        __half2 h23 = __floats2half2_rn(v.z, v.w);
        __half2* d = reinterpret_cast<__half2*>(
            g_xh2 + ((size_t)(s * 1024 + j0 + jj)) * 128 + a4);
        d[0] = h01; d[1] = h23;
    }
    __syncthreads();
#pragma unroll
    for (int it = 0; it < 4; it++) {
        int f = tid + it * 256;
        int a = f >> 3, jb = f & 7;
        __half2 h01 = __floats2half2_rn(t[jb * 4 + 0][a], t[jb * 4 + 1][a]);
        __half2 h23 = __floats2half2_rn(t[jb * 4 + 2][a], t[jb * 4 + 3][a]);
        __half2* d = reinterpret_cast<__half2*>(
            g_xh + ((size_t)(s * 128 + a)) * 1024 + j0 + jb * 4);
        d[0] = h01; d[1] = h23;
    }
}

// ---------------------------------------------------------------------------
// Shared tile-MMA: 8 warps (2M x 4N), M=64, N=128, K-tile=32 fp16.
// A tile: [64 rows][32 k] (4KB, 64B rows SW64). B tile: [128 n][32 k] (8KB).
// ---------------------------------------------------------------------------
#define STAGE_B   12288
#define SM_AS(st) (512u + (st) * STAGE_B)
#define SM_BS(st) (512u + (st) * STAGE_B + 4096u)
#define SMEM_TOT  (512 + 3 * STAGE_B)

__device__ __forceinline__ void mma_tile(float acc[2][4][4], uint32_t As, uint32_t Bs,
                                         int wm, int wn, int lane) {
#pragma unroll
    for (int k16 = 0; k16 < 2; k16++) {
        uint32_t aF[2][4], bF[2][4];
#pragma unroll
        for (int mi = 0; mi < 2; mi++)
            LDSM4(aF[mi], As + swz64((uint32_t)((wm * 32 + mi * 16 + (lane & 15)) * 64
                                                + k16 * 32 + (lane >> 4) * 16)));
#pragma unroll
        for (int nb = 0; nb < 2; nb++)
            LDSM4(bF[nb], Bs + swz64((uint32_t)((wn * 32 + nb * 16 + ((lane >> 4) << 3)
                                                 + (lane & 7)) * 64
                                                + k16 * 32 + ((lane >> 3) & 1) * 16)));
#pragma unroll
        for (int mi = 0; mi < 2; mi++)
#pragma unroll
            for (int nb = 0; nb < 2; nb++) {
                mma16(acc[mi][nb * 2 + 0], aF[mi], &bF[nb][0]);
                mma16(acc[mi][nb * 2 + 1], aF[mi], &bF[nb][2]);
            }
    }
}

// ---------------------------------------------------------------------------
// k1: per (s, 16 i-rows): D[(c,il)][a] = sum_j Ar_c[il][j] * x[j][a]
//     M=64 rows = c*16+il, N=128, K=1024 in 32 tiles of 32. 3-stage ring,
//     3 CTAs/SM. Fused rowsum -> norm in epilogue -> g_Mh (fp16).
// ---------------------------------------------------------------------------
__global__ void __launch_bounds__(256, 3)
k1_gemm(const float* __restrict__ A)
{
    extern __shared__ char sm[];
    const uint32_t sb = cvta_s(sm);
    float* nrm = reinterpret_cast<float*>(sm);   // [64]

    const int tid = threadIdx.x, warp = tid >> 5, lane = tid & 31;
    const int wm = warp & 1, wn = warp >> 1;
    const int s = blockIdx.y, i0 = blockIdx.x * 16;

    const int il = tid >> 4, hx = tid & 15;       // A-load: row il, j-pair {2hx,2hx+1}
    const float* Ab = A + ((size_t)(s * 1024 + i0 + il)) * 5120 + hx * 10;
    const __half* xT = g_xh + (size_t)s * 131072;

    float va[10];
    auto ldA = [&](int kt) {
        const float* At = Ab + kt * 160;
#pragma unroll
        for (int q = 0; q < 5; q++) {
            float2 v = *reinterpret_cast<const float2*>(At + q * 2);
            va[q * 2] = v.x; va[q * 2 + 1] = v.y;
        }
    };
    float rs[4] = {0.f, 0.f, 0.f, 0.f};
    auto stsA = [&](int st) {
        const uint32_t base = sb + SM_AS(st);
#pragma unroll
        for (int c = 0; c < 4; c++) {
            float v0 = va[c], v1 = va[5 + c];     // j=2hx, j=2hx+1
            rs[c] += v0 + v1;
            asm volatile("st.shared.b32 [%0], %1;" ::
                "r"(base + swz64((uint32_t)((c * 16 + il) * 64 + hx * 4))),
                "r"(*(uint32_t*)&__floats2half2_rn(v0, v1)) : "memory");
        }
    };
    auto ldB = [&](int kt, int st) {
        const uint32_t dst = sb + SM_BS(st);
#pragma unroll
        for (int it = 0; it < 2; it++) {
            int f = tid + it * 256;               // < 512 (128 rows x 4 chunks)
            int row = f >> 2, ch = f & 3;
            cpa16(dst + swz64((uint32_t)(row * 64 + ch * 16)),
                  xT + (size_t)row * 1024 + kt * 32 + ch * 8);
        }
    };

    float acc[2][4][4];
#pragma unroll
    for (int mi = 0; mi < 2; mi++)
#pragma unroll
        for (int ni = 0; ni < 4; ni++)
#pragma unroll
            for (int e = 0; e < 4; e++) acc[mi][ni][e] = 0.f;

    // prologue: B0,B1 in flight; A0,A1 staged; regs hold A2
    ldB(0, 0); CPA_COMMIT;
    ldB(1, 1); CPA_COMMIT;
    ldA(0); stsA(0);
    ldA(1); stsA(1);
    ldA(2);

#pragma unroll 1
    for (int kt = 0; kt < 32; kt++) {
        const int st = kt % 3;
        if (kt < 31) { CPA_WAIT1; } else { CPA_WAIT0; }
        __syncthreads();
        if (kt + 2 < 32) { ldB(kt + 2, (kt + 2) % 3); CPA_COMMIT; }
        mma_tile(acc, sb + SM_AS(st), sb + SM_BS(st), wm, wn, lane);
        if (kt + 2 < 32) {
            stsA((kt + 2) % 3);                   // A(kt+2) from regs
            if (kt + 3 < 32) ldA(kt + 3);
        }
    }

    // norm = 1/(rowsum + eps): reduce 16 threads sharing a row
#pragma unroll
    for (int m = 1; m < 16; m <<= 1)
#pragma unroll
        for (int c = 0; c < 4; c++)
            rs[c] += __shfl_xor_sync(0xffffffff, rs[c], m);
    if (hx == 0)
#pragma unroll
        for (int c = 0; c < 4; c++)
            nrm[c * 16 + il] = 1.0f / (rs[c] + EPSV);
    __syncthreads();

    // epilogue: scale by norm, convert fp16, store g_Mh
#pragma unroll
    for (int mi = 0; mi < 2; mi++) {
        int r0 = wm * 32 + mi * 16 + (lane >> 2);
        int r1 = r0 + 8;
        float nm0 = nrm[r0], nm1 = nrm[r1];
        int c0 = r0 >> 4, il0 = r0 & 15;
        int c1 = r1 >> 4, il1 = r1 & 15;
        __half* d0 = g_Mh + (((size_t)(s * 4 + c0)) * 1024 + i0 + il0) * 128;
        __half* d1 = g_Mh + (((size_t)(s * 4 + c1)) * 1024 + i0 + il1) * 128;
#pragma unroll
        for (int n8 = 0; n8 < 4; n8++) {
            int cn = wn * 32 + n8 * 8 + (lane & 3) * 2;
            *reinterpret_cast<__half2*>(d0 + cn) =
                __floats2half2_rn(acc[mi][n8][0] * nm0, acc[mi][n8][1] * nm0);
            *reinterpret_cast<__half2*>(d1 + cn) =
                __floats2half2_rn(acc[mi][n8][2] * nm1, acc[mi][n8][3] * nm1);
        }
    }
}

// ---------------------------------------------------------------------------
// k2: out = tanh([Mn_0..Mn_3, x] @ W2^T). M=64 i, N=128 b, K=640 (20 tiles
// of 32). 3-stage, 3 CTAs/SM, loads issued 2 tiles ahead.
// ---------------------------------------------------------------------------
__global__ void __launch_bounds__(256, 3)
k2_agg(float* __restrict__ out)
{
    extern __shared__ char sm[];
    const uint32_t sb = cvta_s(sm);
    const int tid = threadIdx.x, warp = tid >> 5, lane = tid & 31;
    const int wm = warp & 1, wn = warp >> 1;
    const int s = blockIdx.y, i0 = blockIdx.x * 64;

    auto ldTile = [&](int kt, int st) {
        const int c = kt >> 2, a0 = (kt & 3) * 32;
        const uint32_t ld = sb + SM_AS(st), wd = sb + SM_BS(st);
        {
            int row = tid >> 2, ch = tid & 3;     // L: 64 rows x 4 chunks = 256
            const __half* src = (c < 4)
                ? (g_Mh + (((size_t)(s * 4 + c)) * 1024 + i0 + row) * 128 + a0 + ch * 8)
                : (g_xh2 + ((size_t)(s * 1024 + i0 + row)) * 128 + a0 + ch * 8);
            cpa16(ld + swz64((uint32_t)(row * 64 + ch * 16)), src);
        }
#pragma unroll
        for (int it = 0; it < 2; it++) {          // W: 128 rows x 4 chunks = 512
            int f = tid + it * 256;
            int row = f >> 2, ch = f & 3;
            cpa16(wd + swz64((uint32_t)(row * 64 + ch * 16)),
                  g_W2h + (size_t)row * 640 + kt * 32 + ch * 8);
        }
    };

    float acc[2][4][4];
#pragma unroll
    for (int mi = 0; mi < 2; mi++)
#pragma unroll
        for (int ni = 0; ni < 4; ni++)
#pragma unroll
            for (int e = 0; e < 4; e++) acc[mi][ni][e] = 0.f;

    ldTile(0, 0); CPA_COMMIT;
    ldTile(1, 1); CPA_COMMIT;

#pragma unroll 1
    for (int kt = 0; kt < 20; kt++) {
        const int st = kt % 3;
        if (kt < 19) { CPA_WAIT1; } else { CPA_WAIT0; }
        __syncthreads();
        if (kt + 2 < 20) { ldTile(kt + 2, (kt + 2) % 3); CPA_COMMIT; }
        mma_tile(acc, sb + SM_AS(st), sb + SM_BS(st), wm, wn, lane);
    }

    // epilogue: tanh + fp32 store
#pragma unroll
    for (int mi = 0; mi < 2; mi++) {
        int r0 = i0 + wm * 32 + mi * 16 + (lane >> 2);
        float* o0 = out + ((size_t)(s * 1024) + r0) * 128;
        float* o1 = out + ((size_t)(s * 1024) + r0 + 8) * 128;
#pragma unroll
        for (int n8 = 0; n8 < 4; n8++) {
            int cn = wn * 32 + n8 * 8 + (lane & 3) * 2;
            *reinterpret_cast<float2*>(o0 + cn) =
                make_float2(fasttanh(acc[mi][n8][0]), fasttanh(acc[mi][n8][1]));
            *reinterpret_cast<float2*>(o1 + cn) =
                make_float2(fasttanh(acc[mi][n8][2]), fasttanh(acc[mi][n8][3]));
        }
    }
}

// ---------------------------------------------------------------------------
extern "C" void kernel_launch(void* const* d_in, const int* in_sizes, int n_in,
                              void* d_out, int out_size)
{
    const float* A     = (const float*)d_in[0];
    const float* x     = (const float*)d_in[1];
    const float* w     = (const float*)d_in[2];
    const float* theta = (const float*)d_in[3];
    float* out = (float*)d_out;

    cudaFuncSetAttribute(k1_gemm, cudaFuncAttributeMaxDynamicSharedMemorySize, SMEM_TOT);
    cudaFuncSetAttribute(k2_agg,  cudaFuncAttributeMaxDynamicSharedMemorySize, SMEM_TOT);

    k0_w<<<64, 256>>>(w, theta);
    k0_x<<<dim3(32, 16), 256>>>(x);
    k1_gemm<<<dim3(64, 16), 256, SMEM_TOT>>>(A);
    k2_agg<<<dim3(16, 16), 256, SMEM_TOT>>>(out);
}